// round 8
// baseline (speedup 1.0000x reference)
#include <cuda_runtime.h>
#include <cuda_bf16.h>
#include <mma.h>
#include <math.h>

#define N_NODES 10000
#define N_EDGES 128000
#define E_HALF  64000
#define NF_K    264          // 260 padded to mult of 8

typedef __nv_bfloat16 bf16;

// ---------------- scratch (device globals; no allocations allowed) ----------------
__device__ bf16  g_eaH[(size_t)N_EDGES*640];
__device__ bf16  g_eaL[(size_t)N_EDGES*640];
__device__ bf16  g_nfH[N_NODES*NF_K], g_nfL[N_NODES*NF_K];
__device__ float g_P  [N_NODES*128];
__device__ float g_x1 [N_NODES*64], g_x2[N_NODES*64], g_x3[N_NODES*64], g_x4[N_NODES*64];
__device__ bf16  g_x1H[N_NODES*64], g_x1L[N_NODES*64];
__device__ bf16  g_x2H[N_NODES*64], g_x2L[N_NODES*64];
__device__ bf16  g_x3H[N_NODES*64], g_x3L[N_NODES*64];
__device__ float g_Eu [(size_t)N_EDGES*64];                 // Ebig upper (conv2 edge_attr part)
__device__ bf16  g_HH [(size_t)N_EDGES*64], g_HL[(size_t)N_EDGES*64];
__device__ bf16  g_rM1H[(size_t)N_EDGES*64], g_rM1L[(size_t)N_EDGES*64];
__device__ bf16  g_rM2H[(size_t)N_EDGES*64], g_rM2L[(size_t)N_EDGES*64];
__device__ bf16  g_rM3H[(size_t)N_EDGES*64], g_rM3L[(size_t)N_EDGES*64];
__device__ float g_M4 [(size_t)N_EDGES*64];
// pre-split weights
__device__ bf16 g_W1nH[NF_K*128], g_W1nL[NF_K*128];
__device__ bf16 g_WbH [640*128],  g_WbL [640*128];
__device__ bf16 g_W2nH[64*128],   g_W2nL[64*128];
__device__ bf16 g_W3nH[128*128],  g_W3nL[128*128];
__device__ bf16 g_W4nH[128*128],  g_W4nL[128*128];
__device__ bf16 g_c1wH[64*64], g_c1wL[64*64];
__device__ bf16 g_c2wH[64*64], g_c2wL[64*64];
__device__ bf16 g_c3wH[64*64], g_c3wL[64*64];
__device__ bf16 g_c4wH[64*64], g_c4wL[64*64];
__device__ bf16 g_e2H[64*64],  g_e2L[64*64];
__device__ bf16 g_e3H[128*64], g_e3L[128*64];
__device__ bf16 g_e4H[128*64], g_e4L[128*64];
__device__ float g_inv[N_NODES];
__device__ int   g_cnt[N_NODES];

// ---------------- split helpers ----------------
__device__ __forceinline__ void split1(float v, bf16& h, bf16& l)
{
    h = __float2bfloat16(v);
    l = __float2bfloat16(v - __bfloat162float(h));
}

// =====================================================================
// Split-bf16 tensor-core GEMM, all operands pre-split in gmem.
//   C[M, BN] = (A0h+A0l | A1h+A1l) @ (Bh+Bl)   (drop Al*Bl)
// EPI: 0 node-P, 1 conv1-big, 2 conv2-hidden, 3 conv3/4-hidden, 4 M+scatter
// =====================================================================
template<int BN, int EPI>
__global__ __launch_bounds__(256) void gemm_sb(
    const bf16* __restrict__ A0h, const bf16* __restrict__ A0l, int ldA0, int K0,
    const bf16* __restrict__ A1h, const bf16* __restrict__ A1l, int ldA1, int K1,
    const bf16* __restrict__ Bh_g, const bf16* __restrict__ Bl_g,
    const float* __restrict__ bias,
    float* __restrict__ Cf, int ldC, int M,
    const int* __restrict__ row, const int* __restrict__ col,
    const float* __restrict__ P, const float* __restrict__ E0u,
    const float* __restrict__ rot, const float* __restrict__ rotW,
    float* __restrict__ xsum,
    bf16* __restrict__ Hh_g, bf16* __restrict__ Hl_g)
{
    using namespace nvcuda;
    constexpr int BM = 64, BK = 32;
    constexpr int WN = BN / 4, NT = WN / 16, MT = 2;
    constexpr int AEL = BM * BK, BEL = BK * BN;
    constexpr int TILE_B = (2 * AEL + 2 * BEL) * 2;
    constexpr int CS_B   = BM * BN * 4;
    constexpr int SMEM_B = TILE_B > CS_B ? TILE_B : CS_B;

    __shared__ __align__(16) char sraw[SMEM_B];
    __shared__ int sRow[BM], sCol[BM];
    bf16* Ash = (bf16*)sraw;
    bf16* Asl = Ash + AEL;
    bf16* Bsh = Asl + AEL;
    bf16* Bsl = Bsh + BEL;
    float* Cs = (float*)sraw;

    const int tid  = threadIdx.x;
    const int warp = tid >> 5;
    const int wm   = warp >> 2, wn = warp & 3;
    const int m0   = blockIdx.x * BM;
    const int K    = K0 + K1;

    if (EPI > 0 && tid < BM) {
        int e = m0 + tid;
        sRow[tid] = (e < M) ? row[e] : 0;
        sCol[tid] = (e < M && col) ? col[e] : 0;
    }

    wmma::fragment<wmma::accumulator, 16, 16, 16, float> acc[MT][NT];
#pragma unroll
    for (int mi = 0; mi < MT; mi++)
#pragma unroll
        for (int ni = 0; ni < NT; ni++) wmma::fill_fragment(acc[mi][ni], 0.f);

    for (int kb = 0; kb < K; kb += BK) {
        // ---- A tile: 64 rows x 32 cols, h+l, pure uint4 copies ----
        {
            const int r = tid >> 2;
            const int c8 = (tid & 3) * 8;
            const int m = m0 + r;
            const int kk = kb + c8;
            uint4 vh = make_uint4(0, 0, 0, 0), vl = vh;
            if (m < M && kk < K) {
                if (kk < K0) {
                    const size_t o = (size_t)m * ldA0 + kk;
                    vh = *(const uint4*)(A0h + o);
                    vl = *(const uint4*)(A0l + o);
                } else {
                    const size_t o = (size_t)m * ldA1 + (kk - K0);
                    vh = *(const uint4*)(A1h + o);
                    vl = *(const uint4*)(A1l + o);
                }
            }
            *(uint4*)(Ash + r * BK + c8) = vh;
            *(uint4*)(Asl + r * BK + c8) = vl;
        }
        // ---- B tile: 32 x BN, h+l ----
        {
            constexpr int CPR = BN / 8;            // 8-el chunks per row
            constexpr int T = (BK * CPR) / 256;
#pragma unroll
            for (int t = 0; t < T; t++) {
                const int idx = tid + t * 256;
                const int k = idx / CPR, jc = (idx % CPR) * 8;
                const int kk = kb + k;
                uint4 vh = make_uint4(0, 0, 0, 0), vl = vh;
                if (kk < K) {
                    const size_t o = (size_t)kk * BN + jc;
                    vh = *(const uint4*)(Bh_g + o);
                    vl = *(const uint4*)(Bl_g + o);
                }
                *(uint4*)(Bsh + k * BN + jc) = vh;
                *(uint4*)(Bsl + k * BN + jc) = vl;
            }
        }
        __syncthreads();
#pragma unroll
        for (int ks = 0; ks < 2; ks++) {
            wmma::fragment<wmma::matrix_a, 16, 16, 16, bf16, wmma::row_major> fah[MT], fal[MT];
            wmma::fragment<wmma::matrix_b, 16, 16, 16, bf16, wmma::row_major> fbh[NT], fbl[NT];
#pragma unroll
            for (int mi = 0; mi < MT; mi++) {
                const int off = (wm * 32 + mi * 16) * BK + ks * 16;
                wmma::load_matrix_sync(fah[mi], Ash + off, BK);
                wmma::load_matrix_sync(fal[mi], Asl + off, BK);
            }
#pragma unroll
            for (int ni = 0; ni < NT; ni++) {
                const int off = (ks * 16) * BN + wn * WN + ni * 16;
                wmma::load_matrix_sync(fbh[ni], Bsh + off, BN);
                wmma::load_matrix_sync(fbl[ni], Bsl + off, BN);
            }
#pragma unroll
            for (int mi = 0; mi < MT; mi++)
#pragma unroll
                for (int ni = 0; ni < NT; ni++) {
                    wmma::mma_sync(acc[mi][ni], fah[mi], fbh[ni], acc[mi][ni]);
                    wmma::mma_sync(acc[mi][ni], fah[mi], fbl[ni], acc[mi][ni]);
                    wmma::mma_sync(acc[mi][ni], fal[mi], fbh[ni], acc[mi][ni]);
                }
        }
        __syncthreads();
    }

    // ---- epilogue via smem C tile ----
#pragma unroll
    for (int mi = 0; mi < MT; mi++)
#pragma unroll
        for (int ni = 0; ni < NT; ni++)
            wmma::store_matrix_sync(Cs + (wm * 32 + mi * 16) * BN + wn * WN + ni * 16,
                                    acc[mi][ni], BN, wmma::mem_row_major);
    __syncthreads();

#pragma unroll 4
    for (int idx = tid; idx < BM * BN; idx += 256) {
        const int i = idx / BN, j = idx - i * BN;
        const int m = m0 + i;
        if (m >= M) continue;
        float v = Cs[idx];
        if (EPI == 0) {
            Cf[(size_t)m * ldC + j] = v;
        } else if (EPI == 1) {
            if (j >= 64) {
                Cf[(size_t)m * 64 + (j - 64)] = v;        // Ebig upper half
            } else {
                const int r = sRow[i], c = sCol[i];
                float h = v + P[r * 128 + j] + P[c * 128 + 64 + j] + bias[j];
#pragma unroll
                for (int kk = 0; kk < 4; kk++)
                    h += rot[(size_t)m * 4 + kk] * rotW[kk * 64 + j];
                h = fmaxf(h, 0.f);
                bf16 bh, bl; split1(h, bh, bl);
                Hh_g[(size_t)m * 64 + j] = bh;
                Hl_g[(size_t)m * 64 + j] = bl;
            }
        } else if (EPI == 2 || EPI == 3) {
            const int r = sRow[i], c = sCol[i];
            float h = v + P[r * 128 + j] + P[c * 128 + 64 + j] + bias[j];
            if (EPI == 2) h += E0u[(size_t)m * 64 + j];
            h = fmaxf(h, 0.f);
            bf16 bh, bl; split1(h, bh, bl);
            Hh_g[(size_t)m * 64 + j] = bh;
            Hl_g[(size_t)m * 64 + j] = bl;
        } else { // EPI == 4
            v += bias[j];
            atomicAdd(&xsum[sRow[i] * 64 + j], v);
            if (Cf) Cf[(size_t)m * 64 + j] = v;
            float rv = fmaxf(v, 0.f);
            bf16 bh, bl; split1(rv, bh, bl);
            Hh_g[(size_t)m * 64 + j] = bh;
            Hl_g[(size_t)m * 64 + j] = bl;
        }
    }
}

// ---------------- conversion / prep kernels ----------------
__global__ void conv_eattr_kernel(const float* __restrict__ ea)
{
    const size_t n4 = (size_t)N_EDGES * 640 / 4;
    size_t i = (size_t)blockIdx.x * blockDim.x + threadIdx.x;
    if (i >= n4) return;
    float4 v = ((const float4*)ea)[i];
    bf16 h0, h1, h2, h3, l0, l1, l2, l3;
    split1(v.x, h0, l0); split1(v.y, h1, l1);
    split1(v.z, h2, l2); split1(v.w, h3, l3);
    ((__nv_bfloat162*)g_eaH)[i * 2]     = __nv_bfloat162(h0, h1);
    ((__nv_bfloat162*)g_eaH)[i * 2 + 1] = __nv_bfloat162(h2, h3);
    ((__nv_bfloat162*)g_eaL)[i * 2]     = __nv_bfloat162(l0, l1);
    ((__nv_bfloat162*)g_eaL)[i * 2 + 1] = __nv_bfloat162(l2, l3);
}

__global__ void conv_nf_kernel(const float* __restrict__ xorg, const float* __restrict__ xrot)
{
    int idx = blockIdx.x * blockDim.x + threadIdx.x;
    if (idx >= N_NODES * NF_K) return;
    int n = idx / NF_K, k = idx - n * NF_K;
    float v = 0.f;
    if (k < 256) v = xorg[n * 256 + k];
    else if (k < 260) v = xrot[n * 4 + (k - 256)];
    bf16 h, l; split1(v, h, l);
    g_nfH[idx] = h; g_nfL[idx] = l;
}

// dual-source 128-wide weight pack+split, zero-padded to Kpad
__global__ void wsplit2_kernel(bf16* __restrict__ dh, bf16* __restrict__ dl,
                               const float* __restrict__ srcA, int offA,
                               const float* __restrict__ srcB, int offB,
                               int Kreal, int Kpad)
{
    int idx = blockIdx.x * blockDim.x + threadIdx.x;
    if (idx >= Kpad * 128) return;
    int k = idx >> 7, j = idx & 127;
    float v = 0.f;
    if (k < Kreal) v = (j < 64) ? srcA[(offA + k) * 64 + j] : srcB[(offB + k) * 64 + (j - 64)];
    bf16 h, l; split1(v, h, l);
    dh[idx] = h; dl[idx] = l;
}

// single-source 64-wide weight split
__global__ void wsplit1_kernel(bf16* __restrict__ dh, bf16* __restrict__ dl,
                               const float* __restrict__ src, int off, int Kreal)
{
    int idx = blockIdx.x * blockDim.x + threadIdx.x;
    if (idx >= Kreal * 64) return;
    int k = idx >> 6, j = idx & 63;
    float v = src[(off + k) * 64 + j];
    bf16 h, l; split1(v, h, l);
    dh[idx] = h; dl[idx] = l;
}

__global__ void zero_f_kernel(float* p, long n)
{
    long i = (long)blockIdx.x * blockDim.x + threadIdx.x;
    if (i < n) p[i] = 0.f;
}

__global__ void zero_cnt_kernel()
{
    int i = blockIdx.x * blockDim.x + threadIdx.x;
    if (i < N_NODES) g_cnt[i] = 0;
}

__global__ void count_kernel(const int* __restrict__ row)
{
    int e = blockIdx.x * blockDim.x + threadIdx.x;
    if (e < N_EDGES) atomicAdd(&g_cnt[row[e]], 1);
}

__global__ void invdeg_kernel()
{
    int n = blockIdx.x * blockDim.x + threadIdx.x;
    if (n < N_NODES) g_inv[n] = 1.f / fmaxf((float)g_cnt[n], 1.f);
}

// x = xsum * inv (+relu); optional split-bf16 emission for next node GEMM
__global__ void finalize_kernel(float* __restrict__ x, bf16* __restrict__ xh,
                                bf16* __restrict__ xl, int relu)
{
    int idx = blockIdx.x * blockDim.x + threadIdx.x;
    if (idx >= N_NODES * 64) return;
    int n = idx >> 6;
    float v = x[idx] * g_inv[n];
    if (relu) v = fmaxf(v, 0.f);
    x[idx] = v;
    if (xh) { bf16 h, l; split1(v, h, l); xh[idx] = h; xl[idx] = l; }
}

// out[n,0:4] = normalize(x4[n] @ lin1_w + lin1_b)
__global__ void node_head_kernel(const float* __restrict__ W,
                                 const float* __restrict__ b,
                                 float* __restrict__ out)
{
    int n = blockIdx.x * blockDim.x + threadIdx.x;
    if (n >= N_NODES) return;
    float y0 = b[0], y1 = b[1], y2 = b[2], y3 = b[3];
    const float* xr = g_x4 + (long)n * 64;
#pragma unroll 8
    for (int k = 0; k < 64; k++) {
        float xv = xr[k];
        y0 = fmaf(xv, W[k * 4 + 0], y0);
        y1 = fmaf(xv, W[k * 4 + 1], y1);
        y2 = fmaf(xv, W[k * 4 + 2], y2);
        y3 = fmaf(xv, W[k * 4 + 3], y3);
    }
    float s = y0 * y0 + y1 * y1 + y2 * y2 + y3 * y3;
    float r = 1.f / fmaxf(sqrtf(s), 1e-12f);
    out[n * 4 + 0] = y0 * r;
    out[n * 4 + 1] = y1 * r;
    out[n * 4 + 2] = y2 * r;
    out[n * 4 + 3] = y3 * r;
}

// pred[e] = relu((M4[e]+M4[e+E/2]) @ W1 + b1) @ w2 + b2
__global__ __launch_bounds__(256) void edge_head_kernel(
    const float* __restrict__ W1, const float* __restrict__ b1,
    const float* __restrict__ w2, const float* __restrict__ b2,
    float* __restrict__ out)
{
    __shared__ float sW[64 * 32];
    __shared__ float sb[32];
    int tid = threadIdx.x;
    for (int i = tid; i < 64 * 32; i += 256) sW[i] = W1[i];
    if (tid < 32) sb[tid] = b1[tid];
    __syncthreads();
    int lane = tid & 31, w = tid >> 5;
    int e = blockIdx.x * 8 + w;
    if (e >= E_HALF) return;
    const float* h0 = g_M4 + (long)e * 64;
    const float* h1 = g_M4 + (long)(e + E_HALF) * 64;
    float t = sb[lane];
#pragma unroll 8
    for (int k = 0; k < 64; k++) {
        float h = h0[k] + h1[k];
        t = fmaf(h, sW[k * 32 + lane], t);
    }
    float r = fmaxf(t, 0.f) * w2[lane];
#pragma unroll
    for (int off = 16; off; off >>= 1) r += __shfl_down_sync(0xffffffffu, r, off);
    if (lane == 0) out[e] = r + b2[0];
}

// ---------------- host orchestration ----------------
template <class T>
static void* symaddr_(T& s)
{
    void* p = nullptr;
    cudaGetSymbolAddress(&p, s);
    return p;
}
#define SYM(x) symaddr_(x)

extern "C" void kernel_launch(void* const* d_in, const int* in_sizes, int n_in,
                              void* d_out, int out_size)
{
    (void)in_sizes; (void)n_in; (void)out_size;
    const float* x_org = (const float*)d_in[0];
    const float* x_rot = (const float*)d_in[1];
    const int*   eidx  = (const int*)  d_in[2];
    const float* eattr = (const float*)d_in[3];
    const float* erot  = (const float*)d_in[4];
    const float* c1_w1 = (const float*)d_in[5];  const float* c1_b1 = (const float*)d_in[6];
    const float* c1_w2 = (const float*)d_in[7];  const float* c1_b2 = (const float*)d_in[8];
    const float* c2_w1 = (const float*)d_in[9];  const float* c2_b1 = (const float*)d_in[10];
    const float* c2_w2 = (const float*)d_in[11]; const float* c2_b2 = (const float*)d_in[12];
    const float* c3_w1 = (const float*)d_in[13]; const float* c3_b1 = (const float*)d_in[14];
    const float* c3_w2 = (const float*)d_in[15]; const float* c3_b2 = (const float*)d_in[16];
    const float* c4_w1 = (const float*)d_in[17]; const float* c4_b1 = (const float*)d_in[18];
    const float* c4_w2 = (const float*)d_in[19]; const float* c4_b2 = (const float*)d_in[20];
    const float* lin1_w = (const float*)d_in[21]; const float* lin1_b = (const float*)d_in[22];
    const float* efc_w1 = (const float*)d_in[23]; const float* efc_b1 = (const float*)d_in[24];
    const float* efc_w2 = (const float*)d_in[25]; const float* efc_b2 = (const float*)d_in[26];
    float* out = (float*)d_out;

    const int* row = eidx;
    const int* col = eidx + N_EDGES;

    bf16 *eaH = (bf16*)SYM(g_eaH), *eaL = (bf16*)SYM(g_eaL);
    bf16 *nfH = (bf16*)SYM(g_nfH), *nfL = (bf16*)SYM(g_nfL);
    float *P  = (float*)SYM(g_P);
    float *x1 = (float*)SYM(g_x1), *x2 = (float*)SYM(g_x2);
    float *x3 = (float*)SYM(g_x3), *x4 = (float*)SYM(g_x4);
    bf16 *x1H = (bf16*)SYM(g_x1H), *x1L = (bf16*)SYM(g_x1L);
    bf16 *x2H = (bf16*)SYM(g_x2H), *x2L = (bf16*)SYM(g_x2L);
    bf16 *x3H = (bf16*)SYM(g_x3H), *x3L = (bf16*)SYM(g_x3L);
    float *Eu = (float*)SYM(g_Eu);
    bf16 *HH = (bf16*)SYM(g_HH), *HL = (bf16*)SYM(g_HL);
    bf16 *rM1H = (bf16*)SYM(g_rM1H), *rM1L = (bf16*)SYM(g_rM1L);
    bf16 *rM2H = (bf16*)SYM(g_rM2H), *rM2L = (bf16*)SYM(g_rM2L);
    bf16 *rM3H = (bf16*)SYM(g_rM3H), *rM3L = (bf16*)SYM(g_rM3L);
    float *M4 = (float*)SYM(g_M4);
    bf16 *W1nH = (bf16*)SYM(g_W1nH), *W1nL = (bf16*)SYM(g_W1nL);
    bf16 *WbH = (bf16*)SYM(g_WbH),  *WbL = (bf16*)SYM(g_WbL);
    bf16 *W2nH = (bf16*)SYM(g_W2nH), *W2nL = (bf16*)SYM(g_W2nL);
    bf16 *W3nH = (bf16*)SYM(g_W3nH), *W3nL = (bf16*)SYM(g_W3nL);
    bf16 *W4nH = (bf16*)SYM(g_W4nH), *W4nL = (bf16*)SYM(g_W4nL);
    bf16 *c1wH = (bf16*)SYM(g_c1wH), *c1wL = (bf16*)SYM(g_c1wL);
    bf16 *c2wH = (bf16*)SYM(g_c2wH), *c2wL = (bf16*)SYM(g_c2wL);
    bf16 *c3wH = (bf16*)SYM(g_c3wH), *c3wL = (bf16*)SYM(g_c3wL);
    bf16 *c4wH = (bf16*)SYM(g_c4wH), *c4wL = (bf16*)SYM(g_c4wL);
    bf16 *e2H = (bf16*)SYM(g_e2H), *e2L = (bf16*)SYM(g_e2L);
    bf16 *e3H = (bf16*)SYM(g_e3H), *e3L = (bf16*)SYM(g_e3L);
    bf16 *e4H = (bf16*)SYM(g_e4H), *e4L = (bf16*)SYM(g_e4L);

    const int GE = N_EDGES / 64;               // 2000
    const int GN = (N_NODES + 63) / 64;        // 157
    const int ZB = (N_NODES * 64 + 255) / 256;
    const bf16*  NB = nullptr;
    const float* NF = nullptr;
    const int*   NI = nullptr;

    // ---------- prep / conversions ----------
    {
        size_t n4 = (size_t)N_EDGES * 640 / 4;
        conv_eattr_kernel<<<(unsigned)((n4 + 255) / 256), 256>>>(eattr);
    }
    conv_nf_kernel<<<(N_NODES * NF_K + 255) / 256, 256>>>(x_org, x_rot);
    wsplit2_kernel<<<(NF_K * 128 + 255) / 256, 256>>>(W1nH, W1nL, c1_w1, 0,   c1_w1, 260, 260, NF_K);
    wsplit2_kernel<<<(640 * 128 + 255) / 256, 256>>>(WbH,  WbL,  c1_w1, 520, c2_w1, 128, 640, 640);
    wsplit2_kernel<<<(64  * 128 + 255) / 256, 256>>>(W2nH, W2nL, c2_w1, 0,   c2_w1, 64,  64,  64);
    wsplit2_kernel<<<(128 * 128 + 255) / 256, 256>>>(W3nH, W3nL, c3_w1, 0,   c3_w1, 128, 128, 128);
    wsplit2_kernel<<<(128 * 128 + 255) / 256, 256>>>(W4nH, W4nL, c4_w1, 0,   c4_w1, 128, 128, 128);
    wsplit1_kernel<<<(64 * 64 + 255) / 256, 256>>>(c1wH, c1wL, c1_w2, 0, 64);
    wsplit1_kernel<<<(64 * 64 + 255) / 256, 256>>>(c2wH, c2wL, c2_w2, 0, 64);
    wsplit1_kernel<<<(64 * 64 + 255) / 256, 256>>>(c3wH, c3wL, c3_w2, 0, 64);
    wsplit1_kernel<<<(64 * 64 + 255) / 256, 256>>>(c4wH, c4wL, c4_w2, 0, 64);
    wsplit1_kernel<<<(64  * 64 + 255) / 256, 256>>>(e2H, e2L, c2_w1, 768, 64);
    wsplit1_kernel<<<(128 * 64 + 255) / 256, 256>>>(e3H, e3L, c3_w1, 256, 128);
    wsplit1_kernel<<<(128 * 64 + 255) / 256, 256>>>(e4H, e4L, c4_w1, 256, 128);
    zero_cnt_kernel<<<(N_NODES + 255) / 256, 256>>>();
    count_kernel<<<(N_EDGES + 255) / 256, 256>>>(row);
    invdeg_kernel<<<(N_NODES + 255) / 256, 256>>>();
    zero_f_kernel<<<ZB, 256>>>(x1, (long)N_NODES * 64);
    zero_f_kernel<<<ZB, 256>>>(x2, (long)N_NODES * 64);
    zero_f_kernel<<<ZB, 256>>>(x3, (long)N_NODES * 64);
    zero_f_kernel<<<ZB, 256>>>(x4, (long)N_NODES * 64);

    // ================= conv1 =================
    gemm_sb<128, 0><<<GN, 256>>>(nfH, nfL, NF_K, NF_K, NB, NB, 0, 0,
                                 W1nH, W1nL, NF, P, 128, N_NODES,
                                 NI, NI, NF, NF, NF, NF, nullptr, nullptr, nullptr);
    gemm_sb<128, 1><<<GE, 256>>>(eaH, eaL, 640, 640, NB, NB, 0, 0,
                                 WbH, WbL, c1_b1, Eu, 64, N_EDGES,
                                 row, col, P, NF, erot, c1_w1 + 1160 * 64, nullptr, HH, HL);
    gemm_sb<64, 4><<<GE, 256>>>(HH, HL, 64, 64, NB, NB, 0, 0,
                                c1wH, c1wL, c1_b2, nullptr, 64, N_EDGES,
                                row, NI, NF, NF, NF, NF, x1, rM1H, rM1L);
    finalize_kernel<<<ZB, 256>>>(x1, x1H, x1L, 0);

    // ================= conv2 =================
    gemm_sb<128, 0><<<GN, 256>>>(x1H, x1L, 64, 64, NB, NB, 0, 0,
                                 W2nH, W2nL, NF, P, 128, N_NODES,
                                 NI, NI, NF, NF, NF, NF, nullptr, nullptr, nullptr);
    gemm_sb<64, 2><<<GE, 256>>>(rM1H, rM1L, 64, 64, NB, NB, 0, 0,
                                e2H, e2L, c2_b1, nullptr, 64, N_EDGES,
                                row, col, P, Eu, NF, NF, nullptr, HH, HL);
    gemm_sb<64, 4><<<GE, 256>>>(HH, HL, 64, 64, NB, NB, 0, 0,
                                c2wH, c2wL, c2_b2, nullptr, 64, N_EDGES,
                                row, NI, NF, NF, NF, NF, x2, rM2H, rM2L);
    finalize_kernel<<<ZB, 256>>>(x2, x2H, x2L, 1);

    // ================= conv3 =================
    gemm_sb<128, 0><<<GN, 256>>>(x2H, x2L, 64, 64, x1H, x1L, 64, 64,
                                 W3nH, W3nL, NF, P, 128, N_NODES,
                                 NI, NI, NF, NF, NF, NF, nullptr, nullptr, nullptr);
    gemm_sb<64, 3><<<GE, 256>>>(rM2H, rM2L, 64, 64, rM1H, rM1L, 64, 64,
                                e3H, e3L, c3_b1, nullptr, 64, N_EDGES,
                                row, col, P, NF, NF, NF, nullptr, HH, HL);
    gemm_sb<64, 4><<<GE, 256>>>(HH, HL, 64, 64, NB, NB, 0, 0,
                                c3wH, c3wL, c3_b2, nullptr, 64, N_EDGES,
                                row, NI, NF, NF, NF, NF, x3, rM3H, rM3L);
    finalize_kernel<<<ZB, 256>>>(x3, x3H, x3L, 1);

    // ================= conv4 =================
    gemm_sb<128, 0><<<GN, 256>>>(x3H, x3L, 64, 64, x2H, x2L, 64, 64,
                                 W4nH, W4nL, NF, P, 128, N_NODES,
                                 NI, NI, NF, NF, NF, NF, nullptr, nullptr, nullptr);
    gemm_sb<64, 3><<<GE, 256>>>(rM3H, rM3L, 64, 64, rM2H, rM2L, 64, 64,
                                e4H, e4L, c4_b1, nullptr, 64, N_EDGES,
                                row, col, P, NF, NF, NF, nullptr, HH, HL);
    gemm_sb<64, 4><<<GE, 256>>>(HH, HL, 64, 64, NB, NB, 0, 0,
                                c4wH, c4wL, c4_b2, M4, 64, N_EDGES,
                                row, NI, NF, NF, NF, NF, x4, rM1H, rM1L);  // rM scratch unused
    finalize_kernel<<<ZB, 256>>>(x4, nullptr, nullptr, 1);

    // ================= heads =================
    node_head_kernel<<<(N_NODES + 127) / 128, 128>>>(lin1_w, lin1_b, out);
    edge_head_kernel<<<(E_HALF + 7) / 8, 256>>>(efc_w1, efc_b1, efc_w2, efc_b2,
                                                out + N_NODES * 4);
}

// round 9
// speedup vs baseline: 1.0233x; 1.0233x over previous
#include <cuda_runtime.h>
#include <cuda_bf16.h>
#include <mma.h>
#include <math.h>

#define N_NODES 10000
#define N_EDGES 128000
#define E_HALF  64000
#define NF_K    288          // 260 padded to mult of 32

typedef __nv_bfloat16 bf16;

// ---------------- scratch (device globals; no allocations allowed) ----------------
__device__ bf16  g_eaH[(size_t)N_EDGES*640];
__device__ bf16  g_eaL[(size_t)N_EDGES*640];
__device__ bf16  g_nfH[N_NODES*NF_K], g_nfL[N_NODES*NF_K];
__device__ float g_P  [N_NODES*128];
__device__ float g_x1 [N_NODES*64], g_x2[N_NODES*64], g_x3[N_NODES*64], g_x4[N_NODES*64];
__device__ bf16  g_x1H[N_NODES*64], g_x1L[N_NODES*64];
__device__ bf16  g_x2H[N_NODES*64], g_x2L[N_NODES*64];
__device__ bf16  g_x3H[N_NODES*64], g_x3L[N_NODES*64];
__device__ float g_Eu [(size_t)N_EDGES*64];                 // Ebig upper (conv2 edge_attr part)
__device__ bf16  g_HH [(size_t)N_EDGES*64], g_HL[(size_t)N_EDGES*64];
__device__ bf16  g_rM1H[(size_t)N_EDGES*64], g_rM1L[(size_t)N_EDGES*64];
__device__ bf16  g_rM2H[(size_t)N_EDGES*64], g_rM2L[(size_t)N_EDGES*64];
__device__ bf16  g_rM3H[(size_t)N_EDGES*64], g_rM3L[(size_t)N_EDGES*64];
__device__ float g_M4 [(size_t)N_EDGES*64];
// pre-split weights (rows zero-padded to K used by GEMM)
__device__ bf16 g_W1nH[NF_K*128], g_W1nL[NF_K*128];
__device__ bf16 g_WbH [640*128],  g_WbL [640*128];
__device__ bf16 g_W2nH[64*128],   g_W2nL[64*128];
__device__ bf16 g_W3nH[128*128],  g_W3nL[128*128];
__device__ bf16 g_W4nH[128*128],  g_W4nL[128*128];
__device__ bf16 g_c1wH[64*64], g_c1wL[64*64];
__device__ bf16 g_c2wH[64*64], g_c2wL[64*64];
__device__ bf16 g_c3wH[64*64], g_c3wL[64*64];
__device__ bf16 g_c4wH[64*64], g_c4wL[64*64];
__device__ bf16 g_e2H[64*64],  g_e2L[64*64];
__device__ bf16 g_e3H[128*64], g_e3L[128*64];
__device__ bf16 g_e4H[128*64], g_e4L[128*64];
__device__ float g_inv[N_NODES];
__device__ int   g_cnt[N_NODES];

// ---------------- helpers ----------------
__device__ __forceinline__ void split1(float v, bf16& h, bf16& l)
{
    h = __float2bfloat16(v);
    l = __float2bfloat16(v - __bfloat162float(h));
}

__device__ __forceinline__ void cp16(void* smem, const void* gmem, bool pred)
{
    unsigned s = (unsigned)__cvta_generic_to_shared(smem);
    int sz = pred ? 16 : 0;
    asm volatile("cp.async.cg.shared.global [%0], [%1], 16, %2;\n"
                 :: "r"(s), "l"(gmem), "r"(sz));
}
__device__ __forceinline__ void cp_commit()
{
    asm volatile("cp.async.commit_group;\n");
}
template<int N> __device__ __forceinline__ void cp_wait()
{
    asm volatile("cp.async.wait_group %0;\n" :: "n"(N));
}

// =====================================================================
// Pipelined split-bf16 tensor-core GEMM (2-stage cp.async double buffer)
//   C[M, BN] = (A0h+A0l | A1h+A1l) @ (Bh+Bl)   (AlBl dropped)
//   BM=128, BK=32, 256 threads, warps 4x2, warp tile 32 x BN/2
// EPI: 0 node-P, 1 conv1-big, 2 conv2-hidden, 3 conv3/4-hidden, 4 M+scatter
// =====================================================================
template<int BN, int EPI>
__global__ __launch_bounds__(256) void gemm_pipe(
    const bf16* __restrict__ A0h, const bf16* __restrict__ A0l, int ldA0, int K0,
    const bf16* __restrict__ A1h, const bf16* __restrict__ A1l, int ldA1, int K,
    const bf16* __restrict__ Bh_g, const bf16* __restrict__ Bl_g,
    const float* __restrict__ bias,
    float* __restrict__ Cf, int M,
    const int* __restrict__ row, const int* __restrict__ col,
    const float* __restrict__ P, const float* __restrict__ E0u,
    const float* __restrict__ rot, const float* __restrict__ rotW,
    float* __restrict__ xsum,
    bf16* __restrict__ Hh_g, bf16* __restrict__ Hl_g)
{
    using namespace nvcuda;
    constexpr int BM = 128, BK = 32;
    constexpr int WNSZ = BN / 2, NT = WNSZ / 16, MT = 2;
    constexpr int A_EL = BM * BK;            // elements per h/l array
    constexpr int B_EL = BK * BN;
    constexpr int STAGE = (A_EL + B_EL) * 2 * 2;   // bytes per stage
    constexpr int BCH = BN / 8;              // 8-elem chunks per B row
    constexpr int BOPS = 2 * BK * BCH;       // cp.async ops for B per stage

    extern __shared__ __align__(16) char sraw[];
    __shared__ int sRow[BM], sCol[BM];

    const int tid  = threadIdx.x;
    const int warp = tid >> 5;
    const int wm   = warp >> 1, wn = warp & 1;
    const int m0   = blockIdx.x * BM;

    if (EPI > 0 && tid < BM) {
        int e = m0 + tid;
        sRow[tid] = (e < M) ? row[e] : 0;
        sCol[tid] = (e < M && col) ? col[e] : 0;
    }

    // ---- stage copy: tile at k-offset kb into buffer buf ----
    auto copy_stage = [&](int kb, int buf) {
        char* base = sraw + buf * STAGE;
        bf16* Ash = (bf16*)base;
        bf16* Asl = Ash + A_EL;
        bf16* Bsh = Asl + A_EL;
        bf16* Bsl = Bsh + B_EL;
        // A: 1024 ops (2 arrays x 128 rows x 4 chunks)
#pragma unroll
        for (int t = 0; t < 4; t++) {
            const int id  = tid + t * 256;
            const int c8  = (id & 3) * 8;
            const int r   = (id >> 2) & 127;
            const int arr = id >> 9;
            const int m   = m0 + r;
            const bool ok = (m < M);
            const int ms  = ok ? m : 0;
            const int kk  = kb + c8;
            const bf16* src;
            if (kk < K0) src = (arr ? A0l : A0h) + (size_t)ms * ldA0 + kk;
            else         src = (arr ? A1l : A1h) + (size_t)ms * ldA1 + (kk - K0);
            cp16((arr ? Asl : Ash) + r * BK + c8, src, ok);
        }
        // B
#pragma unroll
        for (int t = 0; t < BOPS / 256; t++) {
            const int id  = tid + t * 256;
            const int jc  = (id % BCH) * 8;
            const int k   = (id / BCH) % BK;
            const int arr = id / (BK * BCH);
            const bf16* src = (arr ? Bl_g : Bh_g) + (size_t)(kb + k) * BN + jc;
            cp16((arr ? Bsl : Bsh) + k * BN + jc, src, true);
        }
    };

    wmma::fragment<wmma::accumulator, 16, 16, 16, float> acc[MT][NT];
#pragma unroll
    for (int mi = 0; mi < MT; mi++)
#pragma unroll
        for (int ni = 0; ni < NT; ni++) wmma::fill_fragment(acc[mi][ni], 0.f);

    const int NIT = K / BK;
    copy_stage(0, 0);
    cp_commit();

    for (int it = 0; it < NIT; it++) {
        const int cur = it & 1;
        if (it + 1 < NIT) {
            copy_stage((it + 1) * BK, (it + 1) & 1);
            cp_commit();
            cp_wait<1>();
        } else {
            cp_wait<0>();
        }
        __syncthreads();

        char* base = sraw + cur * STAGE;
        bf16* Ash = (bf16*)base;
        bf16* Asl = Ash + A_EL;
        bf16* Bsh = Asl + A_EL;
        bf16* Bsl = Bsh + B_EL;
#pragma unroll
        for (int ks = 0; ks < BK / 16; ks++) {
            wmma::fragment<wmma::matrix_a, 16, 16, 16, bf16, wmma::row_major> fah[MT], fal[MT];
            wmma::fragment<wmma::matrix_b, 16, 16, 16, bf16, wmma::row_major> fbh[NT], fbl[NT];
#pragma unroll
            for (int mi = 0; mi < MT; mi++) {
                const int off = (wm * 32 + mi * 16) * BK + ks * 16;
                wmma::load_matrix_sync(fah[mi], Ash + off, BK);
                wmma::load_matrix_sync(fal[mi], Asl + off, BK);
            }
#pragma unroll
            for (int ni = 0; ni < NT; ni++) {
                const int off = (ks * 16) * BN + wn * WNSZ + ni * 16;
                wmma::load_matrix_sync(fbh[ni], Bsh + off, BN);
                wmma::load_matrix_sync(fbl[ni], Bsl + off, BN);
            }
#pragma unroll
            for (int mi = 0; mi < MT; mi++)
#pragma unroll
                for (int ni = 0; ni < NT; ni++) {
                    wmma::mma_sync(acc[mi][ni], fah[mi], fbh[ni], acc[mi][ni]);
                    wmma::mma_sync(acc[mi][ni], fah[mi], fbl[ni], acc[mi][ni]);
                    wmma::mma_sync(acc[mi][ni], fal[mi], fbh[ni], acc[mi][ni]);
                }
        }
        __syncthreads();
    }

    // ---- epilogue via smem C tile (tiles dead; reuse sraw) ----
    float* Cs = (float*)sraw;
#pragma unroll
    for (int mi = 0; mi < MT; mi++)
#pragma unroll
        for (int ni = 0; ni < NT; ni++)
            wmma::store_matrix_sync(Cs + (wm * 32 + mi * 16) * BN + wn * WNSZ + ni * 16,
                                    acc[mi][ni], BN, wmma::mem_row_major);
    __syncthreads();

#pragma unroll 4
    for (int idx = tid; idx < BM * BN; idx += 256) {
        const int i = idx / BN, j = idx - i * BN;
        const int m = m0 + i;
        if (m >= M) continue;
        float v = Cs[idx];
        if (EPI == 0) {
            Cf[(size_t)m * BN + j] = v;
        } else if (EPI == 1) {
            if (j >= 64) {
                Cf[(size_t)m * 64 + (j - 64)] = v;        // Ebig upper half
            } else {
                const int r = sRow[i], c = sCol[i];
                float h = v + P[r * 128 + j] + P[c * 128 + 64 + j] + bias[j];
#pragma unroll
                for (int kk = 0; kk < 4; kk++)
                    h += rot[(size_t)m * 4 + kk] * rotW[kk * 64 + j];
                h = fmaxf(h, 0.f);
                bf16 bh, bl; split1(h, bh, bl);
                Hh_g[(size_t)m * 64 + j] = bh;
                Hl_g[(size_t)m * 64 + j] = bl;
            }
        } else if (EPI == 2 || EPI == 3) {
            const int r = sRow[i], c = sCol[i];
            float h = v + P[r * 128 + j] + P[c * 128 + 64 + j] + bias[j];
            if (EPI == 2) h += E0u[(size_t)m * 64 + j];
            h = fmaxf(h, 0.f);
            bf16 bh, bl; split1(h, bh, bl);
            Hh_g[(size_t)m * 64 + j] = bh;
            Hl_g[(size_t)m * 64 + j] = bl;
        } else { // EPI == 4
            v += bias[j];
            atomicAdd(&xsum[sRow[i] * 64 + j], v);
            if (Cf) Cf[(size_t)m * 64 + j] = v;
            if (Hh_g) {
                float rv = fmaxf(v, 0.f);
                bf16 bh, bl; split1(rv, bh, bl);
                Hh_g[(size_t)m * 64 + j] = bh;
                Hl_g[(size_t)m * 64 + j] = bl;
            }
        }
    }
}

// ---------------- conversion / prep kernels ----------------
__global__ void conv_eattr_kernel(const float* __restrict__ ea)
{
    const size_t n4 = (size_t)N_EDGES * 640 / 4;
    size_t i = (size_t)blockIdx.x * blockDim.x + threadIdx.x;
    if (i >= n4) return;
    float4 v = ((const float4*)ea)[i];
    bf16 h0, h1, h2, h3, l0, l1, l2, l3;
    split1(v.x, h0, l0); split1(v.y, h1, l1);
    split1(v.z, h2, l2); split1(v.w, h3, l3);
    ((__nv_bfloat162*)g_eaH)[i * 2]     = __nv_bfloat162(h0, h1);
    ((__nv_bfloat162*)g_eaH)[i * 2 + 1] = __nv_bfloat162(h2, h3);
    ((__nv_bfloat162*)g_eaL)[i * 2]     = __nv_bfloat162(l0, l1);
    ((__nv_bfloat162*)g_eaL)[i * 2 + 1] = __nv_bfloat162(l2, l3);
}

__global__ void conv_nf_kernel(const float* __restrict__ xorg, const float* __restrict__ xrot)
{
    int idx = blockIdx.x * blockDim.x + threadIdx.x;
    if (idx >= N_NODES * NF_K) return;
    int n = idx / NF_K, k = idx - n * NF_K;
    float v = 0.f;
    if (k < 256) v = xorg[n * 256 + k];
    else if (k < 260) v = xrot[n * 4 + (k - 256)];
    bf16 h, l; split1(v, h, l);
    g_nfH[idx] = h; g_nfL[idx] = l;
}

// dual-source 128-wide weight pack+split, zero-padded to Kpad
__global__ void wsplit2_kernel(bf16* __restrict__ dh, bf16* __restrict__ dl,
                               const float* __restrict__ srcA, int offA,
                               const float* __restrict__ srcB, int offB,
                               int Kreal, int Kpad)
{
    int idx = blockIdx.x * blockDim.x + threadIdx.x;
    if (idx >= Kpad * 128) return;
    int k = idx >> 7, j = idx & 127;
    float v = 0.f;
    if (k < Kreal) v = (j < 64) ? srcA[(offA + k) * 64 + j] : srcB[(offB + k) * 64 + (j - 64)];
    bf16 h, l; split1(v, h, l);
    dh[idx] = h; dl[idx] = l;
}

// single-source 64-wide weight split
__global__ void wsplit1_kernel(bf16* __restrict__ dh, bf16* __restrict__ dl,
                               const float* __restrict__ src, int off, int Kreal)
{
    int idx = blockIdx.x * blockDim.x + threadIdx.x;
    if (idx >= Kreal * 64) return;
    int k = idx >> 6, j = idx & 63;
    float v = src[(off + k) * 64 + j];
    bf16 h, l; split1(v, h, l);
    dh[idx] = h; dl[idx] = l;
}

__global__ void zero_f_kernel(float* p, long n)
{
    long i = (long)blockIdx.x * blockDim.x + threadIdx.x;
    if (i < n) p[i] = 0.f;
}

__global__ void zero_cnt_kernel()
{
    int i = blockIdx.x * blockDim.x + threadIdx.x;
    if (i < N_NODES) g_cnt[i] = 0;
}

__global__ void count_kernel(const int* __restrict__ row)
{
    int e = blockIdx.x * blockDim.x + threadIdx.x;
    if (e < N_EDGES) atomicAdd(&g_cnt[row[e]], 1);
}

__global__ void invdeg_kernel()
{
    int n = blockIdx.x * blockDim.x + threadIdx.x;
    if (n < N_NODES) g_inv[n] = 1.f / fmaxf((float)g_cnt[n], 1.f);
}

// x = xsum * inv (+relu); optional split-bf16 emission for next node GEMM
__global__ void finalize_kernel(float* __restrict__ x, bf16* __restrict__ xh,
                                bf16* __restrict__ xl, int relu)
{
    int idx = blockIdx.x * blockDim.x + threadIdx.x;
    if (idx >= N_NODES * 64) return;
    int n = idx >> 6;
    float v = x[idx] * g_inv[n];
    if (relu) v = fmaxf(v, 0.f);
    x[idx] = v;
    if (xh) { bf16 h, l; split1(v, h, l); xh[idx] = h; xl[idx] = l; }
}

// out[n,0:4] = normalize(x4[n] @ lin1_w + lin1_b)
__global__ void node_head_kernel(const float* __restrict__ W,
                                 const float* __restrict__ b,
                                 float* __restrict__ out)
{
    int n = blockIdx.x * blockDim.x + threadIdx.x;
    if (n >= N_NODES) return;
    float y0 = b[0], y1 = b[1], y2 = b[2], y3 = b[3];
    const float* xr = g_x4 + (long)n * 64;
#pragma unroll 8
    for (int k = 0; k < 64; k++) {
        float xv = xr[k];
        y0 = fmaf(xv, W[k * 4 + 0], y0);
        y1 = fmaf(xv, W[k * 4 + 1], y1);
        y2 = fmaf(xv, W[k * 4 + 2], y2);
        y3 = fmaf(xv, W[k * 4 + 3], y3);
    }
    float s = y0 * y0 + y1 * y1 + y2 * y2 + y3 * y3;
    float r = 1.f / fmaxf(sqrtf(s), 1e-12f);
    out[n * 4 + 0] = y0 * r;
    out[n * 4 + 1] = y1 * r;
    out[n * 4 + 2] = y2 * r;
    out[n * 4 + 3] = y3 * r;
}

// pred[e] = relu((M4[e]+M4[e+E/2]) @ W1 + b1) @ w2 + b2
__global__ __launch_bounds__(256) void edge_head_kernel(
    const float* __restrict__ W1, const float* __restrict__ b1,
    const float* __restrict__ w2, const float* __restrict__ b2,
    float* __restrict__ out)
{
    __shared__ float sW[64 * 32];
    __shared__ float sb[32];
    int tid = threadIdx.x;
    for (int i = tid; i < 64 * 32; i += 256) sW[i] = W1[i];
    if (tid < 32) sb[tid] = b1[tid];
    __syncthreads();
    int lane = tid & 31, w = tid >> 5;
    int e = blockIdx.x * 8 + w;
    if (e >= E_HALF) return;
    const float* h0 = g_M4 + (long)e * 64;
    const float* h1 = g_M4 + (long)(e + E_HALF) * 64;
    float t = sb[lane];
#pragma unroll 8
    for (int k = 0; k < 64; k++) {
        float h = h0[k] + h1[k];
        t = fmaf(h, sW[k * 32 + lane], t);
    }
    float r = fmaxf(t, 0.f) * w2[lane];
#pragma unroll
    for (int off = 16; off; off >>= 1) r += __shfl_down_sync(0xffffffffu, r, off);
    if (lane == 0) out[e] = r + b2[0];
}

// ---------------- host orchestration ----------------
template <class T>
static void* symaddr_(T& s)
{
    void* p = nullptr;
    cudaGetSymbolAddress(&p, s);
    return p;
}
#define SYM(x) symaddr_(x)

extern "C" void kernel_launch(void* const* d_in, const int* in_sizes, int n_in,
                              void* d_out, int out_size)
{
    (void)in_sizes; (void)n_in; (void)out_size;
    const float* x_org = (const float*)d_in[0];
    const float* x_rot = (const float*)d_in[1];
    const int*   eidx  = (const int*)  d_in[2];
    const float* eattr = (const float*)d_in[3];
    const float* erot  = (const float*)d_in[4];
    const float* c1_w1 = (const float*)d_in[5];  const float* c1_b1 = (const float*)d_in[6];
    const float* c1_w2 = (const float*)d_in[7];  const float* c1_b2 = (const float*)d_in[8];
    const float* c2_w1 = (const float*)d_in[9];  const float* c2_b1 = (const float*)d_in[10];
    const float* c2_w2 = (const float*)d_in[11]; const float* c2_b2 = (const float*)d_in[12];
    const float* c3_w1 = (const float*)d_in[13]; const float* c3_b1 = (const float*)d_in[14];
    const float* c3_w2 = (const float*)d_in[15]; const float* c3_b2 = (const float*)d_in[16];
    const float* c4_w1 = (const float*)d_in[17]; const float* c4_b1 = (const float*)d_in[18];
    const float* c4_w2 = (const float*)d_in[19]; const float* c4_b2 = (const float*)d_in[20];
    const float* lin1_w = (const float*)d_in[21]; const float* lin1_b = (const float*)d_in[22];
    const float* efc_w1 = (const float*)d_in[23]; const float* efc_b1 = (const float*)d_in[24];
    const float* efc_w2 = (const float*)d_in[25]; const float* efc_b2 = (const float*)d_in[26];
    float* out = (float*)d_out;

    const int* row = eidx;
    const int* col = eidx + N_EDGES;

    bf16 *eaH = (bf16*)SYM(g_eaH), *eaL = (bf16*)SYM(g_eaL);
    bf16 *nfH = (bf16*)SYM(g_nfH), *nfL = (bf16*)SYM(g_nfL);
    float *P  = (float*)SYM(g_P);
    float *x1 = (float*)SYM(g_x1), *x2 = (float*)SYM(g_x2);
    float *x3 = (float*)SYM(g_x3), *x4 = (float*)SYM(g_x4);
    bf16 *x1H = (bf16*)SYM(g_x1H), *x1L = (bf16*)SYM(g_x1L);
    bf16 *x2H = (bf16*)SYM(g_x2H), *x2L = (bf16*)SYM(g_x2L);
    bf16 *x3H = (bf16*)SYM(g_x3H), *x3L = (bf16*)SYM(g_x3L);
    float *Eu = (float*)SYM(g_Eu);
    bf16 *HH = (bf16*)SYM(g_HH), *HL = (bf16*)SYM(g_HL);
    bf16 *rM1H = (bf16*)SYM(g_rM1H), *rM1L = (bf16*)SYM(g_rM1L);
    bf16 *rM2H = (bf16*)SYM(g_rM2H), *rM2L = (bf16*)SYM(g_rM2L);
    bf16 *rM3H = (bf16*)SYM(g_rM3H), *rM3L = (bf16*)SYM(g_rM3L);
    float *M4 = (float*)SYM(g_M4);
    bf16 *W1nH = (bf16*)SYM(g_W1nH), *W1nL = (bf16*)SYM(g_W1nL);
    bf16 *WbH = (bf16*)SYM(g_WbH),  *WbL = (bf16*)SYM(g_WbL);
    bf16 *W2nH = (bf16*)SYM(g_W2nH), *W2nL = (bf16*)SYM(g_W2nL);
    bf16 *W3nH = (bf16*)SYM(g_W3nH), *W3nL = (bf16*)SYM(g_W3nL);
    bf16 *W4nH = (bf16*)SYM(g_W4nH), *W4nL = (bf16*)SYM(g_W4nL);
    bf16 *c1wH = (bf16*)SYM(g_c1wH), *c1wL = (bf16*)SYM(g_c1wL);
    bf16 *c2wH = (bf16*)SYM(g_c2wH), *c2wL = (bf16*)SYM(g_c2wL);
    bf16 *c3wH = (bf16*)SYM(g_c3wH), *c3wL = (bf16*)SYM(g_c3wL);
    bf16 *c4wH = (bf16*)SYM(g_c4wH), *c4wL = (bf16*)SYM(g_c4wL);
    bf16 *e2H = (bf16*)SYM(g_e2H), *e2L = (bf16*)SYM(g_e2L);
    bf16 *e3H = (bf16*)SYM(g_e3H), *e3L = (bf16*)SYM(g_e3L);
    bf16 *e4H = (bf16*)SYM(g_e4H), *e4L = (bf16*)SYM(g_e4L);

    const int GE = N_EDGES / 128;              // 1000
    const int GN = (N_NODES + 127) / 128;      // 79
    const int ZB = (N_NODES * 64 + 255) / 256;
    const int SM128 = 65536;                   // dyn smem for BN=128
    const int SM64  = 49152;                   // dyn smem for BN=64
    const bf16*  NB = nullptr;
    const float* NF = nullptr;
    const int*   NI = nullptr;

    cudaFuncSetAttribute(gemm_pipe<128, 0>, cudaFuncAttributeMaxDynamicSharedMemorySize, SM128);
    cudaFuncSetAttribute(gemm_pipe<128, 1>, cudaFuncAttributeMaxDynamicSharedMemorySize, SM128);
    cudaFuncSetAttribute(gemm_pipe<64, 2>,  cudaFuncAttributeMaxDynamicSharedMemorySize, SM64);
    cudaFuncSetAttribute(gemm_pipe<64, 3>,  cudaFuncAttributeMaxDynamicSharedMemorySize, SM64);
    cudaFuncSetAttribute(gemm_pipe<64, 4>,  cudaFuncAttributeMaxDynamicSharedMemorySize, SM64);

    // ---------- prep / conversions ----------
    {
        size_t n4 = (size_t)N_EDGES * 640 / 4;
        conv_eattr_kernel<<<(unsigned)((n4 + 255) / 256), 256>>>(eattr);
    }
    conv_nf_kernel<<<(N_NODES * NF_K + 255) / 256, 256>>>(x_org, x_rot);
    wsplit2_kernel<<<(NF_K * 128 + 255) / 256, 256>>>(W1nH, W1nL, c1_w1, 0,   c1_w1, 260, 260, NF_K);
    wsplit2_kernel<<<(640 * 128 + 255) / 256, 256>>>(WbH,  WbL,  c1_w1, 520, c2_w1, 128, 640, 640);
    wsplit2_kernel<<<(64  * 128 + 255) / 256, 256>>>(W2nH, W2nL, c2_w1, 0,   c2_w1, 64,  64,  64);
    wsplit2_kernel<<<(128 * 128 + 255) / 256, 256>>>(W3nH, W3nL, c3_w1, 0,   c3_w1, 128, 128, 128);
    wsplit2_kernel<<<(128 * 128 + 255) / 256, 256>>>(W4nH, W4nL, c4_w1, 0,   c4_w1, 128, 128, 128);
    wsplit1_kernel<<<(64 * 64 + 255) / 256, 256>>>(c1wH, c1wL, c1_w2, 0, 64);
    wsplit1_kernel<<<(64 * 64 + 255) / 256, 256>>>(c2wH, c2wL, c2_w2, 0, 64);
    wsplit1_kernel<<<(64 * 64 + 255) / 256, 256>>>(c3wH, c3wL, c3_w2, 0, 64);
    wsplit1_kernel<<<(64 * 64 + 255) / 256, 256>>>(c4wH, c4wL, c4_w2, 0, 64);
    wsplit1_kernel<<<(64  * 64 + 255) / 256, 256>>>(e2H, e2L, c2_w1, 768, 64);
    wsplit1_kernel<<<(128 * 64 + 255) / 256, 256>>>(e3H, e3L, c3_w1, 256, 128);
    wsplit1_kernel<<<(128 * 64 + 255) / 256, 256>>>(e4H, e4L, c4_w1, 256, 128);
    zero_cnt_kernel<<<(N_NODES + 255) / 256, 256>>>();
    count_kernel<<<(N_EDGES + 255) / 256, 256>>>(row);
    invdeg_kernel<<<(N_NODES + 255) / 256, 256>>>();
    zero_f_kernel<<<ZB, 256>>>(x1, (long)N_NODES * 64);
    zero_f_kernel<<<ZB, 256>>>(x2, (long)N_NODES * 64);
    zero_f_kernel<<<ZB, 256>>>(x3, (long)N_NODES * 64);
    zero_f_kernel<<<ZB, 256>>>(x4, (long)N_NODES * 64);

    // ================= conv1 =================
    gemm_pipe<128, 0><<<GN, 256, SM128>>>(nfH, nfL, NF_K, NF_K, NB, NB, 0, NF_K,
                                          W1nH, W1nL, NF, P, N_NODES,
                                          NI, NI, NF, NF, NF, NF, nullptr, nullptr, nullptr);
    gemm_pipe<128, 1><<<GE, 256, SM128>>>(eaH, eaL, 640, 640, NB, NB, 0, 640,
                                          WbH, WbL, c1_b1, Eu, N_EDGES,
                                          row, col, P, NF, erot, c1_w1 + 1160 * 64, nullptr, HH, HL);
    gemm_pipe<64, 4><<<GE, 256, SM64>>>(HH, HL, 64, 64, NB, NB, 0, 64,
                                        c1wH, c1wL, c1_b2, nullptr, N_EDGES,
                                        row, NI, NF, NF, NF, NF, x1, rM1H, rM1L);
    finalize_kernel<<<ZB, 256>>>(x1, x1H, x1L, 0);

    // ================= conv2 =================
    gemm_pipe<128, 0><<<GN, 256, SM128>>>(x1H, x1L, 64, 64, NB, NB, 0, 64,
                                          W2nH, W2nL, NF, P, N_NODES,
                                          NI, NI, NF, NF, NF, NF, nullptr, nullptr, nullptr);
    gemm_pipe<64, 2><<<GE, 256, SM64>>>(rM1H, rM1L, 64, 64, NB, NB, 0, 64,
                                        e2H, e2L, c2_b1, nullptr, N_EDGES,
                                        row, col, P, Eu, NF, NF, nullptr, HH, HL);
    gemm_pipe<64, 4><<<GE, 256, SM64>>>(HH, HL, 64, 64, NB, NB, 0, 64,
                                        c2wH, c2wL, c2_b2, nullptr, N_EDGES,
                                        row, NI, NF, NF, NF, NF, x2, rM2H, rM2L);
    finalize_kernel<<<ZB, 256>>>(x2, x2H, x2L, 1);

    // ================= conv3 =================
    gemm_pipe<128, 0><<<GN, 256, SM128>>>(x2H, x2L, 64, 64, x1H, x1L, 64, 128,
                                          W3nH, W3nL, NF, P, N_NODES,
                                          NI, NI, NF, NF, NF, NF, nullptr, nullptr, nullptr);
    gemm_pipe<64, 3><<<GE, 256, SM64>>>(rM2H, rM2L, 64, 64, rM1H, rM1L, 64, 128,
                                        e3H, e3L, c3_b1, nullptr, N_EDGES,
                                        row, col, P, NF, NF, NF, nullptr, HH, HL);
    gemm_pipe<64, 4><<<GE, 256, SM64>>>(HH, HL, 64, 64, NB, NB, 0, 64,
                                        c3wH, c3wL, c3_b2, nullptr, N_EDGES,
                                        row, NI, NF, NF, NF, NF, x3, rM3H, rM3L);
    finalize_kernel<<<ZB, 256>>>(x3, x3H, x3L, 1);

    // ================= conv4 =================
    gemm_pipe<128, 0><<<GN, 256, SM128>>>(x3H, x3L, 64, 64, x2H, x2L, 64, 128,
                                          W4nH, W4nL, NF, P, N_NODES,
                                          NI, NI, NF, NF, NF, NF, nullptr, nullptr, nullptr);
    gemm_pipe<64, 3><<<GE, 256, SM64>>>(rM3H, rM3L, 64, 64, rM2H, rM2L, 64, 128,
                                        e4H, e4L, c4_b1, nullptr, N_EDGES,
                                        row, col, P, NF, NF, NF, nullptr, HH, HL);
    gemm_pipe<64, 4><<<GE, 256, SM64>>>(HH, HL, 64, 64, NB, NB, 0, 64,
                                        c4wH, c4wL, c4_b2, M4, N_EDGES,
                                        row, NI, NF, NF, NF, NF, x4, nullptr, nullptr);
    finalize_kernel<<<ZB, 256>>>(x4, nullptr, nullptr, 1);

    // ================= heads =================
    node_head_kernel<<<(N_NODES + 127) / 128, 128>>>(lin1_w, lin1_b, out);
    edge_head_kernel<<<(E_HALF + 7) / 8, 256>>>(efc_w1, efc_b1, efc_w2, efc_b2,
                                                out + N_NODES * 4);
}

// round 12
// speedup vs baseline: 1.0668x; 1.0425x over previous
#include <cuda_runtime.h>
#include <cuda_bf16.h>
#include <mma.h>
#include <math.h>
#include <stdint.h>

#define N_NODES 10000
#define N_EDGES 128000
#define E_HALF  64000

typedef __nv_bfloat16 bf16;

// ---------------- scratch (device globals; no allocations allowed) ----------------
__device__ float g_P   [N_NODES*128];
__device__ float g_x1  [N_NODES*64];
__device__ float g_x2  [N_NODES*64];
__device__ float g_x3  [N_NODES*64];
__device__ float g_x4  [N_NODES*64];
__device__ float g_Eu  [(size_t)N_EDGES*64];   // conv2 edge_attr part (Wbig cols 64..127), compact
__device__ float g_H   [(size_t)N_EDGES*64];
__device__ float g_M1  [(size_t)N_EDGES*64];
__device__ float g_M2  [(size_t)N_EDGES*64];
__device__ float g_M3  [(size_t)N_EDGES*64];
__device__ float g_M4  [(size_t)N_EDGES*64];
__device__ float g_W1n [260*128];
__device__ float g_Wbig[640*128];
__device__ float g_W2n [64*128];
__device__ float g_W3n [128*128];
__device__ float g_W4n [128*128];
__device__ float g_inv [N_NODES];
__device__ int   g_cnt [N_NODES];

// ---------------- split helpers ----------------
__device__ __forceinline__ void split_store4(bf16* ph, bf16* pl, float4 v)
{
    float vv[4] = { v.x, v.y, v.z, v.w };
#pragma unroll
    for (int i = 0; i < 4; i++) {
        bf16 h = __float2bfloat16(vv[i]);
        ph[i] = h;
        pl[i] = __float2bfloat16(vv[i] - __bfloat162float(h));
    }
}

// =====================================================================
// Split-bf16 WMMA GEMM (R6-proven):  C[M,BN] = op(A0|A1) @ B (+bias)
//   A logically [M, K0+K1] fp32 row-major via two pointers, optional relu.
//   B fp32 row-major [K, ldB].  C ~= Ah@Bh + Ah@Bl + Al@Bh.
// EPI modes:
//   0: C = acc                                         (node P GEMMs)
//   1: conv1-big: j>=64 -> Eu[m*64+(j-64)] = acc;
//      j<64 -> H = relu(acc + Pgather + bias + rot@rotW)
//   2: C = relu(acc + Eu + Pgather + bias)             (conv2 hidden)
//   3: C = relu(acc + Pgather + bias)                  (conv3/4 hidden)
//   4: v = acc + bias; C = v; atomicAdd(xsum[row], v)  (M GEMM + scatter)
// =====================================================================
template<int BN, int EPI>
__global__ __launch_bounds__(256) void gemm_bf16(
    const float* __restrict__ A0, int ldA0, int K0,
    const float* __restrict__ A1, int ldA1, int K1, int reluA,
    const float* __restrict__ B, int ldB,
    const float* __restrict__ bias,
    float* __restrict__ C, int ldC, int M,
    const int* __restrict__ row, const int* __restrict__ col,
    const float* __restrict__ P, const float* __restrict__ E0u,
    const float* __restrict__ rot, const float* __restrict__ rotW,
    float* __restrict__ xsum, float* __restrict__ Hout)
{
    using namespace nvcuda;
    constexpr int BM = 64, BK = 32;
    constexpr int WN = BN / 4;
    constexpr int MT = 2, NT = WN / 16;
    constexpr int TILE_BYTES = (2 * BM * BK + 2 * BK * BN) * 2;
    constexpr int CS_BYTES   = BM * BN * 4;
    constexpr int SMEM_BYTES = TILE_BYTES > CS_BYTES ? TILE_BYTES : CS_BYTES;

    __shared__ __align__(16) char sraw[SMEM_BYTES];
    __shared__ int sRow[BM], sCol[BM];
    bf16* Ah = (bf16*)sraw;
    bf16* Al = Ah + BM * BK;
    bf16* Bh = Al + BM * BK;
    bf16* Bl = Bh + BK * BN;
    float* Cs = (float*)sraw;

    const int tid  = threadIdx.x;
    const int warp = tid >> 5;
    const int wm   = warp >> 2, wn = warp & 3;
    const int m0   = blockIdx.x * BM;
    const int K    = K0 + K1;

    if (EPI > 0 && tid < BM) {
        int e = m0 + tid;
        sRow[tid] = (e < M && row) ? row[e] : 0;
        sCol[tid] = (e < M && col) ? col[e] : 0;
    }

    wmma::fragment<wmma::accumulator, 16, 16, 16, float> acc[MT][NT];
#pragma unroll
    for (int mi = 0; mi < MT; mi++)
#pragma unroll
        for (int ni = 0; ni < NT; ni++) wmma::fill_fragment(acc[mi][ni], 0.f);

    for (int kb = 0; kb < K; kb += BK) {
        // ---- A tile: 64 x 32 fp32 -> split bf16 ----
        {
            const int r  = tid >> 2;
            const int m  = m0 + r;
            const int cb = (tid & 3) * 8;
#pragma unroll
            for (int q = 0; q < 2; q++) {
                const int c  = cb + q * 4;
                const int kk = kb + c;
                float4 v = make_float4(0.f, 0.f, 0.f, 0.f);
                if (m < M && kk < K) {
                    v = (kk < K0) ? *(const float4*)(A0 + (size_t)m * ldA0 + kk)
                                  : *(const float4*)(A1 + (size_t)m * ldA1 + (kk - K0));
                }
                if (reluA) {
                    v.x = fmaxf(v.x, 0.f); v.y = fmaxf(v.y, 0.f);
                    v.z = fmaxf(v.z, 0.f); v.w = fmaxf(v.w, 0.f);
                }
                split_store4(Ah + r * BK + c, Al + r * BK + c, v);
            }
        }
        // ---- B tile: 32 x BN ----
        {
            constexpr int JP = BN / 4;
#pragma unroll
            for (int idx = tid; idx < BK * JP; idx += 256) {
                const int k = idx / JP, jc = idx % JP;
                const int kk = kb + k;
                float4 v = make_float4(0.f, 0.f, 0.f, 0.f);
                if (kk < K) v = *(const float4*)(B + (size_t)kk * ldB + jc * 4);
                split_store4(Bh + k * BN + jc * 4, Bl + k * BN + jc * 4, v);
            }
        }
        __syncthreads();
#pragma unroll
        for (int ks = 0; ks < 2; ks++) {
            wmma::fragment<wmma::matrix_a, 16, 16, 16, bf16, wmma::row_major> fah[MT], fal[MT];
            wmma::fragment<wmma::matrix_b, 16, 16, 16, bf16, wmma::row_major> fbh[NT], fbl[NT];
#pragma unroll
            for (int mi = 0; mi < MT; mi++) {
                const int off = (wm * 32 + mi * 16) * BK + ks * 16;
                wmma::load_matrix_sync(fah[mi], Ah + off, BK);
                wmma::load_matrix_sync(fal[mi], Al + off, BK);
            }
#pragma unroll
            for (int ni = 0; ni < NT; ni++) {
                const int off = (ks * 16) * BN + wn * WN + ni * 16;
                wmma::load_matrix_sync(fbh[ni], Bh + off, BN);
                wmma::load_matrix_sync(fbl[ni], Bl + off, BN);
            }
#pragma unroll
            for (int mi = 0; mi < MT; mi++)
#pragma unroll
                for (int ni = 0; ni < NT; ni++) {
                    wmma::mma_sync(acc[mi][ni], fah[mi], fbh[ni], acc[mi][ni]);
                    wmma::mma_sync(acc[mi][ni], fah[mi], fbl[ni], acc[mi][ni]);
                    wmma::mma_sync(acc[mi][ni], fal[mi], fbh[ni], acc[mi][ni]);
                }
        }
        __syncthreads();
    }

    // ---- epilogue via smem C tile (tiles dead; reuse sraw) ----
#pragma unroll
    for (int mi = 0; mi < MT; mi++)
#pragma unroll
        for (int ni = 0; ni < NT; ni++)
            wmma::store_matrix_sync(Cs + (wm * 32 + mi * 16) * BN + wn * WN + ni * 16,
                                    acc[mi][ni], BN, wmma::mem_row_major);
    __syncthreads();

    for (int idx = tid; idx < BM * BN; idx += 256) {
        const int i = idx / BN, j = idx - i * BN;
        const int m = m0 + i;
        if (m >= M) continue;
        float v = Cs[idx];
        if (EPI == 0) {
            C[(size_t)m * ldC + j] = v;
        } else if (EPI == 1) {
            if (j >= 64) {
                C[(size_t)m * 64 + (j - 64)] = v;          // Eu compact
            } else {
                const int r = sRow[i], c = sCol[i];
                float h = v + P[r * 128 + j] + P[c * 128 + 64 + j] + bias[j];
#pragma unroll
                for (int kk = 0; kk < 4; kk++)
                    h += rot[(size_t)m * 4 + kk] * rotW[kk * 64 + j];
                Hout[(size_t)m * 64 + j] = fmaxf(h, 0.f);
            }
        } else if (EPI == 2 || EPI == 3) {
            const int r = sRow[i], c = sCol[i];
            float h = v + P[r * 128 + j] + P[c * 128 + 64 + j] + bias[j];
            if (EPI == 2) h += E0u[(size_t)m * 64 + j];
            C[(size_t)m * 64 + j] = fmaxf(h, 0.f);
        } else { // EPI == 4
            v += bias[j];
            C[(size_t)m * 64 + j] = v;
            atomicAdd(&xsum[sRow[i] * 64 + j], v);
        }
    }
}

// ---------------- misc kernels ----------------
__global__ void pack_kernel(float* __restrict__ dst,
                            const float* __restrict__ srcA, int offA,
                            const float* __restrict__ srcB, int offB, int K)
{
    int idx = blockIdx.x * blockDim.x + threadIdx.x;
    if (idx >= K * 128) return;
    int k = idx >> 7, j = idx & 127;
    dst[idx] = (j < 64) ? srcA[(offA + k) * 64 + j]
                        : srcB[(offB + k) * 64 + (j - 64)];
}

__global__ void zero_f_kernel(float* p, long n)
{
    long i = (long)blockIdx.x * blockDim.x + threadIdx.x;
    if (i < n) p[i] = 0.f;
}
__global__ void zero_cnt_kernel()
{
    int i = blockIdx.x * blockDim.x + threadIdx.x;
    if (i < N_NODES) g_cnt[i] = 0;
}
__global__ void count_kernel(const int* __restrict__ row)
{
    int e = blockIdx.x * blockDim.x + threadIdx.x;
    if (e < N_EDGES) atomicAdd(&g_cnt[row[e]], 1);
}
__global__ void invdeg_kernel()
{
    int n = blockIdx.x * blockDim.x + threadIdx.x;
    if (n < N_NODES) g_inv[n] = 1.f / fmaxf((float)g_cnt[n], 1.f);
}
__global__ void finalize_kernel(float* __restrict__ x, int relu)
{
    int idx = blockIdx.x * blockDim.x + threadIdx.x;
    if (idx >= N_NODES * 64) return;
    int n = idx >> 6;
    float v = x[idx] * g_inv[n];
    x[idx] = relu ? fmaxf(v, 0.f) : v;
}

__global__ void node_head_kernel(const float* __restrict__ W,
                                 const float* __restrict__ b,
                                 float* __restrict__ out)
{
    int n = blockIdx.x * blockDim.x + threadIdx.x;
    if (n >= N_NODES) return;
    float y0 = b[0], y1 = b[1], y2 = b[2], y3 = b[3];
    const float* xr = g_x4 + (long)n * 64;
#pragma unroll 8
    for (int k = 0; k < 64; k++) {
        float xv = xr[k];
        y0 = fmaf(xv, W[k * 4 + 0], y0);
        y1 = fmaf(xv, W[k * 4 + 1], y1);
        y2 = fmaf(xv, W[k * 4 + 2], y2);
        y3 = fmaf(xv, W[k * 4 + 3], y3);
    }
    float s = y0 * y0 + y1 * y1 + y2 * y2 + y3 * y3;
    float r = 1.f / fmaxf(sqrtf(s), 1e-12f);
    out[n * 4 + 0] = y0 * r;
    out[n * 4 + 1] = y1 * r;
    out[n * 4 + 2] = y2 * r;
    out[n * 4 + 3] = y3 * r;
}

__global__ __launch_bounds__(256) void edge_head_kernel(
    const float* __restrict__ W1, const float* __restrict__ b1,
    const float* __restrict__ w2, const float* __restrict__ b2,
    float* __restrict__ out)
{
    __shared__ float sW[64 * 32];
    __shared__ float sb[32];
    int tid = threadIdx.x;
    for (int i = tid; i < 64 * 32; i += 256) sW[i] = W1[i];
    if (tid < 32) sb[tid] = b1[tid];
    __syncthreads();
    int lane = tid & 31, w = tid >> 5;
    int e = blockIdx.x * 8 + w;
    if (e >= E_HALF) return;
    const float* h0 = g_M4 + (long)e * 64;
    const float* h1 = g_M4 + (long)(e + E_HALF) * 64;
    float t = sb[lane];
#pragma unroll 8
    for (int k = 0; k < 64; k++) {
        float h = h0[k] + h1[k];
        t = fmaf(h, sW[k * 32 + lane], t);
    }
    float r = fmaxf(t, 0.f) * w2[lane];
#pragma unroll
    for (int off = 16; off; off >>= 1) r += __shfl_down_sync(0xffffffffu, r, off);
    if (lane == 0) out[e] = r + b2[0];
}

// ---------------- host orchestration ----------------
template <class T>
static void* symaddr_(T& s)
{
    void* p = nullptr;
    cudaGetSymbolAddress(&p, s);
    return p;
}
#define SYM(x) symaddr_(x)

extern "C" void kernel_launch(void* const* d_in, const int* in_sizes, int n_in,
                              void* d_out, int out_size)
{
    (void)in_sizes; (void)n_in; (void)out_size;
    const float* x_org = (const float*)d_in[0];
    const float* x_rot = (const float*)d_in[1];
    const int*   eidx  = (const int*)  d_in[2];
    const float* eattr = (const float*)d_in[3];
    const float* erot  = (const float*)d_in[4];
    const float* c1_w1 = (const float*)d_in[5];  const float* c1_b1 = (const float*)d_in[6];
    const float* c1_w2 = (const float*)d_in[7];  const float* c1_b2 = (const float*)d_in[8];
    const float* c2_w1 = (const float*)d_in[9];  const float* c2_b1 = (const float*)d_in[10];
    const float* c2_w2 = (const float*)d_in[11]; const float* c2_b2 = (const float*)d_in[12];
    const float* c3_w1 = (const float*)d_in[13]; const float* c3_b1 = (const float*)d_in[14];
    const float* c3_w2 = (const float*)d_in[15]; const float* c3_b2 = (const float*)d_in[16];
    const float* c4_w1 = (const float*)d_in[17]; const float* c4_b1 = (const float*)d_in[18];
    const float* c4_w2 = (const float*)d_in[19]; const float* c4_b2 = (const float*)d_in[20];
    const float* lin1_w = (const float*)d_in[21]; const float* lin1_b = (const float*)d_in[22];
    const float* efc_w1 = (const float*)d_in[23]; const float* efc_b1 = (const float*)d_in[24];
    const float* efc_w2 = (const float*)d_in[25]; const float* efc_b2 = (const float*)d_in[26];
    float* out = (float*)d_out;

    const int* row = eidx;
    const int* col = eidx + N_EDGES;

    float *P  = (float*)SYM(g_P);
    float *x1 = (float*)SYM(g_x1), *x2 = (float*)SYM(g_x2);
    float *x3 = (float*)SYM(g_x3), *x4 = (float*)SYM(g_x4);
    float *Eu = (float*)SYM(g_Eu), *H = (float*)SYM(g_H);
    float *M1 = (float*)SYM(g_M1), *M2 = (float*)SYM(g_M2);
    float *M3 = (float*)SYM(g_M3), *M4 = (float*)SYM(g_M4);
    float *W1n = (float*)SYM(g_W1n), *Wbig = (float*)SYM(g_Wbig);
    float *W2n = (float*)SYM(g_W2n);
    float *W3n = (float*)SYM(g_W3n), *W4n = (float*)SYM(g_W4n);

    const int GE = N_EDGES / 64;               // 2000
    const int GN = (N_NODES + 63) / 64;        // 157
    const int ZB = (N_NODES * 64 + 255) / 256;
    const float* NF = nullptr;
    const int*   NI = nullptr;

    // ---- launches 1-5 (prep), launch 6 = BIG GEMM (ncu -s 5 -c 1 captures it) ----
    pack_kernel<<<(260 * 128 + 255) / 256, 256>>>(W1n,  c1_w1, 0,   c1_w1, 260, 260);   // 1
    pack_kernel<<<(640 * 128 + 255) / 256, 256>>>(Wbig, c1_w1, 520, c2_w1, 128, 640);   // 2
    gemm_bf16<128, 0><<<GN, 256>>>(x_org, 256, 256, x_rot, 4, 4, 0,                     // 3
                                   W1n, 128, NF, P, 128, N_NODES,
                                   NI, NI, NF, NF, NF, NF, nullptr, nullptr);
    zero_cnt_kernel<<<(N_NODES + 255) / 256, 256>>>();                                  // 4
    count_kernel<<<(N_EDGES + 255) / 256, 256>>>(row);                                  // 5
    // BIG fused edge GEMM: Eu = (eattr@Wbig)[:,64:] ; H = relu((eattr@Wbig)[:,:64] + gather + rot)
    gemm_bf16<128, 1><<<GE, 256>>>(eattr, 640, 640, NF, 0, 0, 0,                        // 6 <- profiled
                                   Wbig, 128, c1_b1, Eu, 128, N_EDGES,
                                   row, col, P, NF, erot, c1_w1 + 1160 * 64, nullptr, H);

    // ---- remaining prep ----
    invdeg_kernel<<<(N_NODES + 255) / 256, 256>>>();
    zero_f_kernel<<<ZB, 256>>>(x1, (long)N_NODES * 64);
    zero_f_kernel<<<ZB, 256>>>(x2, (long)N_NODES * 64);
    zero_f_kernel<<<ZB, 256>>>(x3, (long)N_NODES * 64);
    zero_f_kernel<<<ZB, 256>>>(x4, (long)N_NODES * 64);
    pack_kernel<<<(64  * 128 + 255) / 256, 256>>>(W2n, c2_w1, 0, c2_w1, 64,  64);
    pack_kernel<<<(128 * 128 + 255) / 256, 256>>>(W3n, c3_w1, 0, c3_w1, 128, 128);
    pack_kernel<<<(128 * 128 + 255) / 256, 256>>>(W4n, c4_w1, 0, c4_w1, 128, 128);

    // ================= conv1 (rest) =================
    gemm_bf16<64, 4><<<GE, 256>>>(H, 64, 64, NF, 0, 0, 0,
                                  c1_w2, 64, c1_b2, M1, 64, N_EDGES,
                                  row, NI, NF, NF, NF, NF, x1, nullptr);
    finalize_kernel<<<ZB, 256>>>(x1, 0);

    // ================= conv2 =================
    gemm_bf16<128, 0><<<GN, 256>>>(x1, 64, 64, NF, 0, 0, 0,
                                   W2n, 128, NF, P, 128, N_NODES,
                                   NI, NI, NF, NF, NF, NF, nullptr, nullptr);
    gemm_bf16<64, 2><<<GE, 256>>>(M1, 64, 64, NF, 0, 0, 1,
                                  c2_w1 + 768 * 64, 64, c2_b1, H, 64, N_EDGES,
                                  row, col, P, Eu, NF, NF, nullptr, nullptr);
    gemm_bf16<64, 4><<<GE, 256>>>(H, 64, 64, NF, 0, 0, 0,
                                  c2_w2, 64, c2_b2, M2, 64, N_EDGES,
                                  row, NI, NF, NF, NF, NF, x2, nullptr);
    finalize_kernel<<<ZB, 256>>>(x2, 1);

    // ================= conv3 =================
    gemm_bf16<128, 0><<<GN, 256>>>(x2, 64, 64, x1, 64, 64, 0,
                                   W3n, 128, NF, P, 128, N_NODES,
                                   NI, NI, NF, NF, NF, NF, nullptr, nullptr);
    gemm_bf16<64, 3><<<GE, 256>>>(M2, 64, 64, M1, 64, 64, 1,
                                  c3_w1 + 256 * 64, 64, c3_b1, H, 64, N_EDGES,
                                  row, col, P, NF, NF, NF, nullptr, nullptr);
    gemm_bf16<64, 4><<<GE, 256>>>(H, 64, 64, NF, 0, 0, 0,
                                  c3_w2, 64, c3_b2, M3, 64, N_EDGES,
                                  row, NI, NF, NF, NF, NF, x3, nullptr);
    finalize_kernel<<<ZB, 256>>>(x3, 1);

    // ================= conv4 =================
    gemm_bf16<128, 0><<<GN, 256>>>(x3, 64, 64, x2, 64, 64, 0,
                                   W4n, 128, NF, P, 128, N_NODES,
                                   NI, NI, NF, NF, NF, NF, nullptr, nullptr);
    gemm_bf16<64, 3><<<GE, 256>>>(M3, 64, 64, M2, 64, 64, 1,
                                  c4_w1 + 256 * 64, 64, c4_b1, H, 64, N_EDGES,
                                  row, col, P, NF, NF, NF, nullptr, nullptr);
    gemm_bf16<64, 4><<<GE, 256>>>(H, 64, 64, NF, 0, 0, 0,
                                  c4_w2, 64, c4_b2, M4, 64, N_EDGES,
                                  row, NI, NF, NF, NF, NF, x4, nullptr);
    finalize_kernel<<<ZB, 256>>>(x4, 1);

    // ================= heads =================
    node_head_kernel<<<(N_NODES + 127) / 128, 128>>>(lin1_w, lin1_b, out);
    edge_head_kernel<<<(E_HALF + 7) / 8, 256>>>(efc_w1, efc_b1, efc_w2, efc_b2,
                                                out + N_NODES * 4);
}